// round 13
// baseline (speedup 1.0000x reference)
#include <cuda_runtime.h>
#include <cuda_fp16.h>
#include <cstdint>

#define T_TOK 1024
#define HDIM  2048
#define NEXP  16
#define IDIM  1408
#define SI    2816
#define TOPK  4

typedef unsigned long long ull;
typedef unsigned int u32;

// ---------------- scratch (device globals; no allocation allowed) ----------------
__device__ int    g_cnt[NEXP];
__device__ int    g_tok[NEXP * T_TOK];
__device__ float  g_tw [NEXP * T_TOK];
__device__ int    g_tid4[T_TOK * TOPK];
__device__ float  g_twk4[T_TOK * TOPK];
__device__ __half g_act [(size_t)NEXP * T_TOK * IDIM];  // routed activations (fp16)
__device__ __half g_acts[(size_t)T_TOK * SI];           // shared activations (fp16)
// fp16 k-pair-packed operands (u32 = (h[2k], h[2k+1]) for one n)
__device__ u32 g_xp  [(size_t)T_TOK * (HDIM / 2)];
__device__ u32 g_wgup[(size_t)NEXP * (HDIM / 2) * (2 * IDIM)];
__device__ u32 g_wdnp[(size_t)NEXP * (IDIM / 2) * HDIM];
__device__ u32 g_sgup[(size_t)(HDIM / 2) * (2 * SI)];
__device__ u32 g_sdnp[(size_t)(SI / 2) * HDIM];

// ---------------- helpers ----------------
__device__ __forceinline__ u32 h2(float lo, float hi) {
    __half2 h = __floats2half2_rn(lo, hi);
    return *reinterpret_cast<u32*>(&h);
}
__device__ __forceinline__ u32 smem_u32(const void* p) {
    u32 a;
    asm("{ .reg .u64 t; cvta.to.shared.u64 t, %1; cvt.u32.u64 %0, t; }" : "=r"(a) : "l"(p));
    return a;
}
__device__ __forceinline__ void cpa16(u32 dst, const void* src) {
    asm volatile("cp.async.cg.shared.global [%0], [%1], 16;" :: "r"(dst), "l"(src) : "memory");
}
#define CP_COMMIT() asm volatile("cp.async.commit_group;" ::: "memory")
#define CP_WAIT1()  asm volatile("cp.async.wait_group 1;" ::: "memory")

// fp16 MMA m16n8k16, fp32 accumulate
__device__ __forceinline__ void mma16(float* d, const u32* a, const u32* b) {
    asm volatile(
        "mma.sync.aligned.m16n8k16.row.col.f32.f16.f16.f32 "
        "{%0,%1,%2,%3}, {%4,%5,%6,%7}, {%8,%9}, {%0,%1,%2,%3};"
        : "+f"(d[0]), "+f"(d[1]), "+f"(d[2]), "+f"(d[3])
        : "r"(a[0]), "r"(a[1]), "r"(a[2]), "r"(a[3]), "r"(b[0]), "r"(b[1]));
}
__device__ __forceinline__ float silu_f(float g) { return g / (1.f + expf(-g)); }

// ---------------- router (exact fp32) ----------------
__global__ void router_kernel(const float* __restrict__ x,
                              const float* __restrict__ gw,
                              const float* __restrict__ bias,
                              int* __restrict__ tid4, float* __restrict__ twk4)
{
    int t = blockIdx.x;
    int tid = threadIdx.x;            // 128 threads: 16 experts x 8 lanes
    int e = tid >> 3, r = tid & 7;
    const float4* x4 = reinterpret_cast<const float4*>(x + (size_t)t * HDIM);
    const float4* w4 = reinterpret_cast<const float4*>(gw + (size_t)e * HDIM);
    float s = 0.f;
    #pragma unroll 4
    for (int j = r; j < HDIM / 4; j += 8) {
        float4 a = x4[j], b = w4[j];
        s += a.x * b.x + a.y * b.y + a.z * b.z + a.w * b.w;
    }
    #pragma unroll
    for (int o = 4; o > 0; o >>= 1) s += __shfl_down_sync(0xffffffffu, s, o, 8);
    __shared__ float logit[NEXP];
    if (r == 0) logit[e] = s;
    __syncthreads();
    if (tid == 0) {
        float sc[NEXP], sb[NEXP];
        #pragma unroll
        for (int i = 0; i < NEXP; i++) {
            sc[i] = 1.f / (1.f + expf(-logit[i]));
            sb[i] = sc[i] + bias[i];
        }
        float gsc[4];
        #pragma unroll
        for (int g = 0; g < 4; g++) {
            const float* p = sb + g * 4;
            float m1 = p[0]; int i1 = 0;
            for (int i = 1; i < 4; i++) if (p[i] > m1) { m1 = p[i]; i1 = i; }
            float m2 = -1e30f;
            for (int i = 0; i < 4; i++) if (i != i1 && p[i] > m2) m2 = p[i];
            gsc[g] = m1 + m2;
        }
        int g1 = 0; for (int g = 1; g < 4; g++) if (gsc[g] > gsc[g1]) g1 = g;
        int g2 = (g1 == 0) ? 1 : 0;
        for (int g = 0; g < 4; g++) if (g != g1 && gsc[g] > gsc[g2]) g2 = g;
        bool allow[NEXP];
        for (int i = 0; i < NEXP; i++) { int g = i >> 2; allow[i] = (g == g1 || g == g2); }
        int ids[TOPK]; float wsum = 0.f;
        for (int k = 0; k < TOPK; k++) {
            int best = 0; float bv = -1e30f;
            for (int i = 0; i < NEXP; i++)
                if (allow[i] && sb[i] > bv) { bv = sb[i]; best = i; }
            allow[best] = false;
            ids[k] = best;
            wsum += sc[best];
        }
        for (int k = 0; k < TOPK; k++) {
            tid4[t * TOPK + k] = ids[k];
            twk4[t * TOPK + k] = sc[ids[k]] / wsum;
        }
    }
}

// ---------------- deterministic per-expert token lists ----------------
__global__ void build_lists(const int* __restrict__ tid4, const float* __restrict__ twk4,
                            int* __restrict__ cnt, int* __restrict__ tok, float* __restrict__ tw)
{
    int e = threadIdx.x;
    if (e >= NEXP) return;
    int c = 0;
    for (int t = 0; t < T_TOK; t++) {
        int4  id = reinterpret_cast<const int4*>(tid4)[t];
        float4 w = reinterpret_cast<const float4*>(twk4)[t];
        if (id.x == e) { tok[e * T_TOK + c] = t; tw[e * T_TOK + c] = w.x * 2.5f; c++; }
        if (id.y == e) { tok[e * T_TOK + c] = t; tw[e * T_TOK + c] = w.y * 2.5f; c++; }
        if (id.z == e) { tok[e * T_TOK + c] = t; tw[e * T_TOK + c] = w.z * 2.5f; c++; }
        if (id.w == e) { tok[e * T_TOK + c] = t; tw[e * T_TOK + c] = w.w * 2.5f; c++; }
    }
    cnt[e] = c;
}

// ---------------- weight pre-pack: fp32 [.., 2k2/2k2+1 rows, N] -> u32 pairs ----------------
__global__ void pack_pairs(const float* __restrict__ in, uint4* __restrict__ out,
                           long long items, int Nq)
{
    long long stride = (long long)gridDim.x * blockDim.x;
    for (long long i = (long long)blockIdx.x * blockDim.x + threadIdx.x; i < items; i += stride) {
        long long r = i / Nq;
        int c = (int)(i - r * Nq) * 4;
        const float* r0 = in + 2 * r * (long long)(Nq * 4) + c;
        const float* r1 = r0 + Nq * 4;
        float4 a = *(const float4*)r0;
        float4 b = *(const float4*)r1;
        uint4 o;
        o.x = h2(a.x, b.x); o.y = h2(a.y, b.y); o.z = h2(a.z, b.z); o.w = h2(a.w, b.w);
        out[i] = o;
    }
}

// x: fp32 -> fp16 (k-contiguous rows are naturally pair-packed)
__global__ void cvt_h(const float* __restrict__ in, uint2* __restrict__ out, int items)
{
    int i = blockIdx.x * blockDim.x + threadIdx.x;
    if (i >= items) return;
    float4 v = reinterpret_cast<const float4*>(in)[i];
    uint2 o;
    o.x = h2(v.x, v.y); o.y = h2(v.z, v.w);
    out[i] = o;
}

// =====================================================================
// gate_up GEMM, fp16 mma.sync + cp.async 3-stage, BK=64 halves, 256 thr.
// CTA tile 128m x (128g + 128u); 8 warps = 2m x 4n; warp 64m x (32g+32u).
// Stage: As[128][36] u32 (32 data + 4 pad), Bg[32][136], Bu[32][136].
// =====================================================================
#define SAW2 36
#define SBW  136
#define GU_STG (128 * SAW2 + 2 * 32 * SBW)   // 13312 u32
#define GU_DYN (3 * GU_STG * 4 + 1024)
__global__ void __launch_bounds__(256)
gu_mma(const u32* __restrict__ Xp, const u32* __restrict__ Wp,
       __half* __restrict__ ACT,
       const int* __restrict__ tok, const float* __restrict__ tw,
       const int* __restrict__ cnt, int Iw, int K)
{
    extern __shared__ u32 sm[];
    int*   tokSm = (int*)(sm + 3 * GU_STG);
    float* twSm  = (float*)(tokSm + 128);

    int e = blockIdx.z;
    int cn = cnt ? cnt[e] : T_TOK;
    int m0 = blockIdx.y * 128;
    if (m0 >= cn) return;
    int n0 = blockIdx.x * 128;
    int K2 = K >> 1;
    int ldW = 2 * Iw;
    const u32* We = Wp + (size_t)e * K2 * ldW;
    __half* actE = ACT + (size_t)e * T_TOK * Iw;

    int tid = threadIdx.x;
    if (tid < 128) {
        int s = m0 + tid; int a; float wv;
        if (tok) {
            const int* tokE = tok + e * T_TOK;
            const float* twE = tw + e * T_TOK;
            if (s < cn) { a = tokE[s]; wv = twE[s]; } else { a = 0; wv = 0.f; }
        } else { a = s; wv = 1.f; }
        tokSm[tid] = a; twSm[tid] = wv;
    }
    __syncthreads();

    // staging: per thread 4 A chunks + 4 Bg chunks + 4 Bu chunks (16B each)
    int arow = tid >> 1, kw = (tid & 1) * 16;
    const u32* aCur = Xp + (size_t)tokSm[arow] * K2 + kw;
    int bk2 = tid >> 3, bc4 = (tid & 7) * 4;
    const u32* gCur = We + (size_t)bk2 * ldW + n0 + bc4;

    u32 su = smem_u32(sm);
    u32 dA = (u32)(arow * SAW2 + kw) * 4;
    u32 dG = (u32)(128 * SAW2 + bk2 * SBW + bc4) * 4;
    u32 dU = dG + (u32)(32 * SBW) * 4;

    // warp mapping: 2m x 4n; warp tile 64m x (32g + 32u)
    int w = tid >> 5, lane = tid & 31;
    int g = lane >> 2, t = lane & 3;
    int wm = (w & 1) * 64, wn = (w >> 1) * 32;

    float ag[4][4][4], au[4][4][4];
    #pragma unroll
    for (int i = 0; i < 4; i++)
        #pragma unroll
        for (int j = 0; j < 4; j++)
            #pragma unroll
            for (int q = 0; q < 4; q++) { ag[i][j][q] = 0.f; au[i][j][q] = 0.f; }

    const int NK = K2 / 32;                  // BK = 64 halves = 32 u32
    int nstage = 0, wbuf = 0;
    #pragma unroll
    for (int s = 0; s < 2; ++s) {
        if (nstage < NK) {
            u32 b = su + (u32)wbuf * (GU_STG * 4);
            #pragma unroll
            for (int i = 0; i < 4; i++) {
                cpa16(b + dA + 16 * i, aCur + 4 * i);
                cpa16(b + dG + 128 * i, gCur + 32 * i);
                cpa16(b + dU + 128 * i, gCur + Iw + 32 * i);
            }
            aCur += 32; gCur += (size_t)32 * ldW;
            nstage++; if (++wbuf == 3) wbuf = 0;
        }
        CP_COMMIT();
    }

    int rbuf = 0;
    for (int it = 0; it < NK; ++it) {
        CP_WAIT1();
        __syncthreads();
        if (nstage < NK) {
            u32 b = su + (u32)wbuf * (GU_STG * 4);
            #pragma unroll
            for (int i = 0; i < 4; i++) {
                cpa16(b + dA + 16 * i, aCur + 4 * i);
                cpa16(b + dG + 128 * i, gCur + 32 * i);
                cpa16(b + dU + 128 * i, gCur + Iw + 32 * i);
            }
            aCur += 32; gCur += (size_t)32 * ldW;
            nstage++; if (++wbuf == 3) wbuf = 0;
        }
        CP_COMMIT();

        const u32* As = sm + rbuf * GU_STG;
        const u32* Bg = As + 128 * SAW2;
        const u32* Bu = Bg + 32 * SBW;
        #pragma unroll
        for (int ks = 0; ks < 4; ++ks) {
            int k0 = ks * 8;
            u32 af[4][4];
            #pragma unroll
            for (int mt = 0; mt < 4; ++mt) {
                int r = wm + mt * 16 + g;
                af[mt][0] = As[r * SAW2 + k0 + t];
                af[mt][1] = As[(r + 8) * SAW2 + k0 + t];
                af[mt][2] = As[r * SAW2 + k0 + t + 4];
                af[mt][3] = As[(r + 8) * SAW2 + k0 + t + 4];
            }
            #pragma unroll
            for (int nt = 0; nt < 4; ++nt) {
                int n = wn + nt * 8 + g;
                u32 bg2[2] = { Bg[(k0 + t) * SBW + n], Bg[(k0 + t + 4) * SBW + n] };
                u32 bu2[2] = { Bu[(k0 + t) * SBW + n], Bu[(k0 + t + 4) * SBW + n] };
                #pragma unroll
                for (int mt = 0; mt < 4; ++mt) {
                    mma16(ag[mt][nt], af[mt], bg2);
                    mma16(au[mt][nt], af[mt], bu2);
                }
            }
        }
        if (++rbuf == 3) rbuf = 0;
    }

    // epilogue: silu(g)*u*w -> act (fp16)
    #pragma unroll
    for (int mt = 0; mt < 4; ++mt) {
        int l0 = wm + mt * 16 + g;
        int s0 = m0 + l0, s1 = s0 + 8;
        bool v0 = s0 < cn, v1 = s1 < cn;
        float w0 = twSm[l0], w1 = twSm[l0 + 8];
        __half* o0 = actE + (size_t)s0 * Iw + n0 + wn;
        __half* o1 = actE + (size_t)s1 * Iw + n0 + wn;
        #pragma unroll
        for (int nt = 0; nt < 4; ++nt) {
            int c = nt * 8 + 2 * t;
            if (v0) {
                *(u32*)(o0 + c) = h2(silu_f(ag[mt][nt][0]) * au[mt][nt][0] * w0,
                                     silu_f(ag[mt][nt][1]) * au[mt][nt][1] * w0);
            }
            if (v1) {
                *(u32*)(o1 + c) = h2(silu_f(ag[mt][nt][2]) * au[mt][nt][2] * w1,
                                     silu_f(ag[mt][nt][3]) * au[mt][nt][3] * w1);
            }
        }
    }
}

// =====================================================================
// down-proj GEMM, fp16 mma.sync + cp.async 3-stage, BK=64 halves, 256 thr.
// CTA tile 128m x 256n; 8 warps = 2m x 4n; warp tile 64m x 64n.
// Stage: As[128][36], Bs[32][264]. routed: atomicAdd; shared: store.
// =====================================================================
#define SBD 264
#define DN_STG (128 * SAW2 + 32 * SBD)   // 13056 u32
#define DN_DYN (3 * DN_STG * 4 + 512)
__global__ void __launch_bounds__(256)
down_mma(const u32* __restrict__ Ap, const u32* __restrict__ Wp,
         float* __restrict__ OUT, const int* __restrict__ tok,
         const int* __restrict__ cnt, int K, int accum)
{
    extern __shared__ u32 sm[];
    int* tokSm = (int*)(sm + 3 * DN_STG);

    int e = blockIdx.z;
    int cn = cnt ? cnt[e] : T_TOK;
    int m0 = blockIdx.y * 128;
    if (m0 >= cn) return;
    int n0 = blockIdx.x * 256;
    int K2 = K >> 1;
    const u32* Ae = Ap + (size_t)e * T_TOK * K2;
    const u32* Be = Wp + (size_t)e * K2 * HDIM;

    int tid = threadIdx.x;
    if (tid < 128) {
        int s = m0 + tid;
        tokSm[tid] = tok ? ((s < cn) ? tok[e * T_TOK + s] : 0) : s;
    }
    __syncthreads();

    // staging: per thread 4 A chunks + 8 B chunks (16B each)
    int arow = tid >> 1, kw = (tid & 1) * 16;
    const u32* aCur = Ae + (size_t)(m0 + arow) * K2 + kw;
    int bk2 = tid >> 3, bc4 = (tid & 7) * 4;
    const u32* bCur = Be + (size_t)bk2 * HDIM + n0 + bc4;

    u32 su = smem_u32(sm);
    u32 dA = (u32)(arow * SAW2 + kw) * 4;
    u32 dB = (u32)(128 * SAW2 + bk2 * SBD + bc4) * 4;

    int w = tid >> 5, lane = tid & 31;
    int g = lane >> 2, t = lane & 3;
    int wm = (w & 1) * 64, wn = (w >> 1) * 64;

    float ac[4][8][4];
    #pragma unroll
    for (int i = 0; i < 4; i++)
        #pragma unroll
        for (int j = 0; j < 8; j++)
            #pragma unroll
            for (int q = 0; q < 4; q++) ac[i][j][q] = 0.f;

    const int NK = K2 / 32;
    int nstage = 0, wbuf = 0;
    #pragma unroll
    for (int s = 0; s < 2; ++s) {
        if (nstage < NK) {
            u32 b = su + (u32)wbuf * (DN_STG * 4);
            #pragma unroll
            for (int i = 0; i < 4; i++) cpa16(b + dA + 16 * i, aCur + 4 * i);
            #pragma unroll
            for (int i = 0; i < 8; i++) cpa16(b + dB + 128 * i, bCur + 32 * i);
            aCur += 32; bCur += (size_t)32 * HDIM;
            nstage++; if (++wbuf == 3) wbuf = 0;
        }
        CP_COMMIT();
    }

    int rbuf = 0;
    for (int it = 0; it < NK; ++it) {
        CP_WAIT1();
        __syncthreads();
        if (nstage < NK) {
            u32 b = su + (u32)wbuf * (DN_STG * 4);
            #pragma unroll
            for (int i = 0; i < 4; i++) cpa16(b + dA + 16 * i, aCur + 4 * i);
            #pragma unroll
            for (int i = 0; i < 8; i++) cpa16(b + dB + 128 * i, bCur + 32 * i);
            aCur += 32; bCur += (size_t)32 * HDIM;
            nstage++; if (++wbuf == 3) wbuf = 0;
        }
        CP_COMMIT();

        const u32* As = sm + rbuf * DN_STG;
        const u32* Bs = As + 128 * SAW2;
        #pragma unroll
        for (int ks = 0; ks < 4; ++ks) {
            int k0 = ks * 8;
            u32 af[4][4];
            #pragma unroll
            for (int mt = 0; mt < 4; ++mt) {
                int r = wm + mt * 16 + g;
                af[mt][0] = As[r * SAW2 + k0 + t];
                af[mt][1] = As[(r + 8) * SAW2 + k0 + t];
                af[mt][2] = As[r * SAW2 + k0 + t + 4];
                af[mt][3] = As[(r + 8) * SAW2 + k0 + t + 4];
            }
            #pragma unroll
            for (int nt = 0; nt < 8; ++nt) {
                int n = wn + nt * 8 + g;
                u32 bf2[2] = { Bs[(k0 + t) * SBD + n], Bs[(k0 + t + 4) * SBD + n] };
                #pragma unroll
                for (int mt = 0; mt < 4; ++mt)
                    mma16(ac[mt][nt], af[mt], bf2);
            }
        }
        if (++rbuf == 3) rbuf = 0;
    }

    #pragma unroll
    for (int mt = 0; mt < 4; ++mt) {
        int l0 = wm + mt * 16 + g;
        int s0 = m0 + l0, s1 = s0 + 8;
        bool v0 = s0 < cn, v1 = s1 < cn;
        float* o0 = OUT + (size_t)tokSm[l0] * HDIM + n0 + wn;
        float* o1 = OUT + (size_t)tokSm[l0 + 8] * HDIM + n0 + wn;
        #pragma unroll
        for (int nt = 0; nt < 8; ++nt) {
            int c = nt * 8 + 2 * t;
            if (accum) {
                if (v0) { atomicAdd(o0 + c, ac[mt][nt][0]); atomicAdd(o0 + c + 1, ac[mt][nt][1]); }
                if (v1) { atomicAdd(o1 + c, ac[mt][nt][2]); atomicAdd(o1 + c + 1, ac[mt][nt][3]); }
            } else {
                if (v0) { float2 r; r.x = ac[mt][nt][0]; r.y = ac[mt][nt][1]; *(float2*)(o0 + c) = r; }
                if (v1) { float2 r; r.x = ac[mt][nt][2]; r.y = ac[mt][nt][3]; *(float2*)(o1 + c) = r; }
            }
        }
    }
}

// ---------------- launch ----------------
extern "C" void kernel_launch(void* const* d_in, const int* in_sizes, int n_in,
                              void* d_out, int out_size)
{
    const float* x    = (const float*)d_in[0];
    const float* gw   = (const float*)d_in[1];
    const float* bias = (const float*)d_in[2];
    const float* wgu  = (const float*)d_in[3];
    const float* wdn  = (const float*)d_in[4];
    const float* sgu  = (const float*)d_in[5];
    const float* sdn  = (const float*)d_in[6];
    float* out = (float*)d_out;

    void *p_cnt, *p_tok, *p_tw, *p_t4, *p_w4, *p_act, *p_acts;
    void *p_xp, *p_wgup, *p_wdnp, *p_sgup, *p_sdnp;
    cudaGetSymbolAddress(&p_cnt,  g_cnt);
    cudaGetSymbolAddress(&p_tok,  g_tok);
    cudaGetSymbolAddress(&p_tw,   g_tw);
    cudaGetSymbolAddress(&p_t4,   g_tid4);
    cudaGetSymbolAddress(&p_w4,   g_twk4);
    cudaGetSymbolAddress(&p_act,  g_act);
    cudaGetSymbolAddress(&p_acts, g_acts);
    cudaGetSymbolAddress(&p_xp,   g_xp);
    cudaGetSymbolAddress(&p_wgup, g_wgup);
    cudaGetSymbolAddress(&p_wdnp, g_wdnp);
    cudaGetSymbolAddress(&p_sgup, g_sgup);
    cudaGetSymbolAddress(&p_sdnp, g_sdnp);

    cudaFuncSetAttribute(gu_mma,   cudaFuncAttributeMaxDynamicSharedMemorySize, GU_DYN);
    cudaFuncSetAttribute(down_mma, cudaFuncAttributeMaxDynamicSharedMemorySize, DN_DYN);

    // 1) router + deterministic dispatch lists (exact fp32)
    router_kernel<<<T_TOK, 128>>>(x, gw, bias, (int*)p_t4, (float*)p_w4);
    build_lists<<<1, 16>>>((const int*)p_t4, (const float*)p_w4,
                           (int*)p_cnt, (int*)p_tok, (float*)p_tw);

    // 2) pre-pack operands to fp16 k-pair format
    {
        long long it_wgu = (long long)NEXP * (HDIM / 2) * (2 * IDIM) / 4;
        long long it_wdn = (long long)NEXP * (IDIM / 2) * HDIM / 4;
        long long it_sgu = (long long)(HDIM / 2) * (2 * SI) / 4;
        long long it_sdn = (long long)(SI / 2) * HDIM / 4;
        pack_pairs<<<(int)((it_wgu + 255) / 256), 256>>>(wgu, (uint4*)p_wgup, it_wgu, (2 * IDIM) / 4);
        pack_pairs<<<(int)((it_wdn + 255) / 256), 256>>>(wdn, (uint4*)p_wdnp, it_wdn, HDIM / 4);
        pack_pairs<<<(int)((it_sgu + 255) / 256), 256>>>(sgu, (uint4*)p_sgup, it_sgu, (2 * SI) / 4);
        pack_pairs<<<(int)((it_sdn + 255) / 256), 256>>>(sdn, (uint4*)p_sdnp, it_sdn, HDIM / 4);
        int it_x = T_TOK * HDIM / 4;
        cvt_h<<<(it_x + 255) / 256, 256>>>(x, (uint2*)p_xp, it_x);
    }

    // 3) gate_up + silu
    gu_mma<<<dim3(SI / 128, T_TOK / 128, 1), 256, GU_DYN>>>(
        (const u32*)p_xp, (const u32*)p_sgup, (__half*)p_acts,
        nullptr, nullptr, nullptr, SI, HDIM);
    gu_mma<<<dim3(IDIM / 128, T_TOK / 128, NEXP), 256, GU_DYN>>>(
        (const u32*)p_xp, (const u32*)p_wgup, (__half*)p_act,
        (const int*)p_tok, (const float*)p_tw, (const int*)p_cnt, IDIM, HDIM);

    // 4) down-proj: shared writes out (init), routed accumulates
    down_mma<<<dim3(HDIM / 256, T_TOK / 128, 1), 256, DN_DYN>>>(
        (const u32*)p_acts, (const u32*)p_sdnp, out, nullptr, nullptr, SI, 0);
    down_mma<<<dim3(HDIM / 256, T_TOK / 128, NEXP), 256, DN_DYN>>>(
        (const u32*)p_act, (const u32*)p_wdnp, out, (const int*)p_tok,
        (const int*)p_cnt, IDIM, 1);
}

// round 15
// speedup vs baseline: 1.1198x; 1.1198x over previous
#include <cuda_runtime.h>
#include <cuda_fp16.h>
#include <cstdint>

#define T_TOK 1024
#define HDIM  2048
#define NEXP  16
#define IDIM  1408
#define SI    2816
#define TOPK  4

typedef unsigned long long ull;
typedef unsigned int u32;

// ---------------- scratch (device globals; no allocation allowed) ----------------
__device__ int    g_cnt[NEXP];
__device__ int    g_tok[NEXP * T_TOK];
__device__ float  g_tw [NEXP * T_TOK];
__device__ int    g_tid4[T_TOK * TOPK];
__device__ float  g_twk4[T_TOK * TOPK];
__device__ __half g_act [(size_t)NEXP * T_TOK * IDIM];  // routed activations (fp16)
__device__ __half g_acts[(size_t)T_TOK * SI];           // shared activations (fp16)

// ---------------- helpers ----------------
__device__ __forceinline__ u32 h2(float lo, float hi) {
    __half2 h = __floats2half2_rn(lo, hi);
    return *reinterpret_cast<u32*>(&h);
}
// fp16 MMA m16n8k16, fp32 accumulate
__device__ __forceinline__ void mma16(float* d, const u32* a, const u32* b) {
    asm volatile(
        "mma.sync.aligned.m16n8k16.row.col.f32.f16.f16.f32 "
        "{%0,%1,%2,%3}, {%4,%5,%6,%7}, {%8,%9}, {%0,%1,%2,%3};"
        : "+f"(d[0]), "+f"(d[1]), "+f"(d[2]), "+f"(d[3])
        : "r"(a[0]), "r"(a[1]), "r"(a[2]), "r"(a[3]), "r"(b[0]), "r"(b[1]));
}
__device__ __forceinline__ float silu_f(float g) { return g / (1.f + expf(-g)); }

// ---------------- zero-init of out ----------------
__global__ void zero_out(float4* __restrict__ p, int n)
{
    int i = blockIdx.x * blockDim.x + threadIdx.x;
    if (i < n) p[i] = make_float4(0.f, 0.f, 0.f, 0.f);
}

// ---------------- router (exact fp32) ----------------
__global__ void router_kernel(const float* __restrict__ x,
                              const float* __restrict__ gw,
                              const float* __restrict__ bias,
                              int* __restrict__ tid4, float* __restrict__ twk4)
{
    int t = blockIdx.x;
    int tid = threadIdx.x;            // 128 threads: 16 experts x 8 lanes
    int e = tid >> 3, r = tid & 7;
    const float4* x4 = reinterpret_cast<const float4*>(x + (size_t)t * HDIM);
    const float4* w4 = reinterpret_cast<const float4*>(gw + (size_t)e * HDIM);
    float s = 0.f;
    #pragma unroll 4
    for (int j = r; j < HDIM / 4; j += 8) {
        float4 a = x4[j], b = w4[j];
        s += a.x * b.x + a.y * b.y + a.z * b.z + a.w * b.w;
    }
    #pragma unroll
    for (int o = 4; o > 0; o >>= 1) s += __shfl_down_sync(0xffffffffu, s, o, 8);
    __shared__ float logit[NEXP];
    if (r == 0) logit[e] = s;
    __syncthreads();
    if (tid == 0) {
        float sc[NEXP], sb[NEXP];
        #pragma unroll
        for (int i = 0; i < NEXP; i++) {
            sc[i] = 1.f / (1.f + expf(-logit[i]));
            sb[i] = sc[i] + bias[i];
        }
        float gsc[4];
        #pragma unroll
        for (int g = 0; g < 4; g++) {
            const float* p = sb + g * 4;
            float m1 = p[0]; int i1 = 0;
            for (int i = 1; i < 4; i++) if (p[i] > m1) { m1 = p[i]; i1 = i; }
            float m2 = -1e30f;
            for (int i = 0; i < 4; i++) if (i != i1 && p[i] > m2) m2 = p[i];
            gsc[g] = m1 + m2;
        }
        int g1 = 0; for (int g = 1; g < 4; g++) if (gsc[g] > gsc[g1]) g1 = g;
        int g2 = (g1 == 0) ? 1 : 0;
        for (int g = 0; g < 4; g++) if (g != g1 && gsc[g] > gsc[g2]) g2 = g;
        bool allow[NEXP];
        for (int i = 0; i < NEXP; i++) { int g = i >> 2; allow[i] = (g == g1 || g == g2); }
        int ids[TOPK]; float wsum = 0.f;
        for (int k = 0; k < TOPK; k++) {
            int best = 0; float bv = -1e30f;
            for (int i = 0; i < NEXP; i++)
                if (allow[i] && sb[i] > bv) { bv = sb[i]; best = i; }
            allow[best] = false;
            ids[k] = best;
            wsum += sc[best];
        }
        for (int k = 0; k < TOPK; k++) {
            tid4[t * TOPK + k] = ids[k];
            twk4[t * TOPK + k] = sc[ids[k]] / wsum;
        }
    }
}

// ---------------- deterministic per-expert token lists ----------------
__global__ void build_lists(const int* __restrict__ tid4, const float* __restrict__ twk4,
                            int* __restrict__ cnt, int* __restrict__ tok, float* __restrict__ tw)
{
    int e = threadIdx.x;
    if (e >= NEXP) return;
    int c = 0;
    for (int t = 0; t < T_TOK; t++) {
        int4  id = reinterpret_cast<const int4*>(tid4)[t];
        float4 w = reinterpret_cast<const float4*>(twk4)[t];
        if (id.x == e) { tok[e * T_TOK + c] = t; tw[e * T_TOK + c] = w.x * 2.5f; c++; }
        if (id.y == e) { tok[e * T_TOK + c] = t; tw[e * T_TOK + c] = w.y * 2.5f; c++; }
        if (id.z == e) { tok[e * T_TOK + c] = t; tw[e * T_TOK + c] = w.z * 2.5f; c++; }
        if (id.w == e) { tok[e * T_TOK + c] = t; tw[e * T_TOK + c] = w.w * 2.5f; c++; }
    }
    cnt[e] = c;
}

// =====================================================================
// COMBINED gate_up GEMM (routed z<16 + shared z==16 in one launch).
// fp16 mma.sync m16n8k16; CTA tile 128m x (128g+128u); 8 warps = 2m x 4n;
// warp tile 64m x (32g + 32u). act = silu(g)*u*w (fp16 out). Exact R9 body.
// =====================================================================
#define SAW 20
#define SBW 136
__global__ void __launch_bounds__(256)
gu_comb(const float* __restrict__ X,
        const float* __restrict__ Wr, const float* __restrict__ Ws,
        __half* __restrict__ ACTr, __half* __restrict__ ACTs,
        const int* __restrict__ tok, const float* __restrict__ tw,
        const int* __restrict__ cnt)
{
    __shared__ u32 As[128 * SAW];
    __shared__ u32 Bg[16 * SBW];
    __shared__ u32 Bu[16 * SBW];
    __shared__ int   tokSm[128];
    __shared__ float twSm[128];

    int z = blockIdx.z;
    bool routed = (z < NEXP);
    if (routed && blockIdx.x >= IDIM / 128) return;
    int Iw = routed ? IDIM : SI;
    int e  = routed ? z : 0;
    int cn = routed ? cnt[e] : T_TOK;
    int m0 = blockIdx.y * 128;
    if (m0 >= cn) return;
    int n0 = blockIdx.x * 128;
    const int K = HDIM;
    int ldW = 2 * Iw;
    const float* We = routed ? (Wr + (size_t)e * K * ldW) : Ws;
    __half* actE = routed ? (ACTr + (size_t)e * T_TOK * IDIM) : ACTs;
    const int*   tokE = routed ? (tok + e * T_TOK) : nullptr;
    const float* twE  = routed ? (tw  + e * T_TOK) : nullptr;

    int tid = threadIdx.x;
    if (tid < 128) {
        int s = m0 + tid; int a; float wv;
        if (routed) {
            if (s < cn) { a = tokE[s]; wv = twE[s]; } else { a = 0; wv = 0.f; }
        } else { a = s; wv = 1.f; }
        tokSm[tid] = a; twSm[tid] = wv;
    }
    __syncthreads();

    // staging mapping
    int arow = tid >> 1, kw = (tid & 1) * 8;
    const float* aP = X + (size_t)tokSm[arow] * K + kw * 2;
    int bk2 = tid >> 4, bn = (tid & 15) * 4;
    const float* gP0 = We + (size_t)(2 * bk2) * ldW + n0 + bn;
    const float* gP1 = gP0 + ldW;
    const float* uP0 = gP0 + Iw;
    const float* uP1 = gP1 + Iw;

    // warp mapping: 2m x 4n
    int w = tid >> 5, lane = tid & 31;
    int g = lane >> 2, t = lane & 3;
    int wm = (w & 1) * 64, wn = (w >> 1) * 32;

    float ag[4][4][4], au[4][4][4];
    #pragma unroll
    for (int i = 0; i < 4; i++)
        #pragma unroll
        for (int j = 0; j < 4; j++)
            #pragma unroll
            for (int q = 0; q < 4; q++) { ag[i][j][q] = 0.f; au[i][j][q] = 0.f; }

    float4 pa[4];
    float4 pg0[2], pg1[2], pu0[2], pu1[2];
    #pragma unroll
    for (int i = 0; i < 4; i++) pa[i] = *(const float4*)(aP + 4 * i);
    #pragma unroll
    for (int i = 0; i < 2; i++) {
        pg0[i] = *(const float4*)(gP0 + 64 * i);
        pg1[i] = *(const float4*)(gP1 + 64 * i);
        pu0[i] = *(const float4*)(uP0 + 64 * i);
        pu1[i] = *(const float4*)(uP1 + 64 * i);
    }

    const int NK = K / 32;
    for (int it = 0; it < NK; ++it) {
        {
            uint4 w0, w1;
            w0.x = h2(pa[0].x, pa[0].y); w0.y = h2(pa[0].z, pa[0].w);
            w0.z = h2(pa[1].x, pa[1].y); w0.w = h2(pa[1].z, pa[1].w);
            w1.x = h2(pa[2].x, pa[2].y); w1.y = h2(pa[2].z, pa[2].w);
            w1.z = h2(pa[3].x, pa[3].y); w1.w = h2(pa[3].z, pa[3].w);
            *(uint4*)&As[arow * SAW + kw]     = w0;
            *(uint4*)&As[arow * SAW + kw + 4] = w1;
            #pragma unroll
            for (int i = 0; i < 2; i++) {
                uint4 bg, bu;
                bg.x = h2(pg0[i].x, pg1[i].x); bg.y = h2(pg0[i].y, pg1[i].y);
                bg.z = h2(pg0[i].z, pg1[i].z); bg.w = h2(pg0[i].w, pg1[i].w);
                bu.x = h2(pu0[i].x, pu1[i].x); bu.y = h2(pu0[i].y, pu1[i].y);
                bu.z = h2(pu0[i].z, pu1[i].z); bu.w = h2(pu0[i].w, pu1[i].w);
                *(uint4*)&Bg[bk2 * SBW + bn + 64 * i] = bg;
                *(uint4*)&Bu[bk2 * SBW + bn + 64 * i] = bu;
            }
        }
        __syncthreads();

        if (it + 1 < NK) {
            const float* aN  = aP + (it + 1) * 32;
            const float* gN0 = gP0 + (size_t)(it + 1) * 32 * ldW;
            const float* gN1 = gN0 + ldW;
            const float* uN0 = gN0 + Iw;
            const float* uN1 = gN1 + Iw;
            #pragma unroll
            for (int i = 0; i < 4; i++) pa[i] = *(const float4*)(aN + 4 * i);
            #pragma unroll
            for (int i = 0; i < 2; i++) {
                pg0[i] = *(const float4*)(gN0 + 64 * i);
                pg1[i] = *(const float4*)(gN1 + 64 * i);
                pu0[i] = *(const float4*)(uN0 + 64 * i);
                pu1[i] = *(const float4*)(uN1 + 64 * i);
            }
        }

        #pragma unroll
        for (int ks = 0; ks < 2; ++ks) {
            int k0 = ks * 8;
            u32 af[4][4];
            #pragma unroll
            for (int mt = 0; mt < 4; ++mt) {
                int r = wm + mt * 16 + g;
                af[mt][0] = As[r * SAW + k0 + t];
                af[mt][1] = As[(r + 8) * SAW + k0 + t];
                af[mt][2] = As[r * SAW + k0 + t + 4];
                af[mt][3] = As[(r + 8) * SAW + k0 + t + 4];
            }
            #pragma unroll
            for (int nt = 0; nt < 4; ++nt) {
                int n = wn + nt * 8 + g;
                u32 bg2[2] = { Bg[(k0 + t) * SBW + n], Bg[(k0 + t + 4) * SBW + n] };
                u32 bu2[2] = { Bu[(k0 + t) * SBW + n], Bu[(k0 + t + 4) * SBW + n] };
                #pragma unroll
                for (int mt = 0; mt < 4; ++mt) {
                    mma16(ag[mt][nt], af[mt], bg2);
                    mma16(au[mt][nt], af[mt], bu2);
                }
            }
        }
        __syncthreads();
    }

    // epilogue: silu(g)*u*w -> act (fp16)
    #pragma unroll
    for (int mt = 0; mt < 4; ++mt) {
        int l0 = wm + mt * 16 + g;
        int s0 = m0 + l0, s1 = s0 + 8;
        bool v0 = s0 < cn, v1 = s1 < cn;
        float w0 = twSm[l0], w1 = twSm[l0 + 8];
        __half* o0 = actE + (size_t)s0 * Iw + n0 + wn;
        __half* o1 = actE + (size_t)s1 * Iw + n0 + wn;
        #pragma unroll
        for (int nt = 0; nt < 4; ++nt) {
            int c = nt * 8 + 2 * t;
            if (v0) {
                *(u32*)(o0 + c) = h2(silu_f(ag[mt][nt][0]) * au[mt][nt][0] * w0,
                                     silu_f(ag[mt][nt][1]) * au[mt][nt][1] * w0);
            }
            if (v1) {
                *(u32*)(o1 + c) = h2(silu_f(ag[mt][nt][2]) * au[mt][nt][2] * w1,
                                     silu_f(ag[mt][nt][3]) * au[mt][nt][3] * w1);
            }
        }
    }
}

// =====================================================================
// COMBINED down-proj GEMM (routed z<16 + shared z==16), all atomicAdd
// into zero-initialized out. CTA tile 128m x 256n; 8 warps = 2m x 4n;
// warp tile 64m x 64n. Exact R9 body.
// =====================================================================
#define SBD 264
__global__ void __launch_bounds__(256)
down_comb(const __half* __restrict__ Ar, const __half* __restrict__ Ash,
          const float* __restrict__ Wr, const float* __restrict__ Ws,
          float* __restrict__ OUT,
          const int* __restrict__ tok, const int* __restrict__ cnt)
{
    __shared__ u32 As[128 * SAW];
    __shared__ u32 Bs[16 * SBD];
    __shared__ int tokSm[128];

    int z = blockIdx.z;
    bool routed = (z < NEXP);
    int K  = routed ? IDIM : SI;
    int e  = routed ? z : 0;
    int cn = routed ? cnt[e] : T_TOK;
    int m0 = blockIdx.y * 128;
    if (m0 >= cn) return;
    int n0 = blockIdx.x * 256;
    const __half* Ae = routed ? (Ar + (size_t)e * T_TOK * IDIM) : Ash;
    const float*  Be = routed ? (Wr + (size_t)e * (size_t)IDIM * HDIM) : Ws;

    int tid = threadIdx.x;
    if (tid < 128) {
        int s = m0 + tid;
        tokSm[tid] = routed ? ((s < cn) ? tok[e * T_TOK + s] : 0) : s;
    }
    __syncthreads();

    int arow = tid >> 1, kw = (tid & 1) * 8;
    const __half* aP = Ae + (size_t)(m0 + arow) * K + kw * 2;
    int bk2 = tid >> 4, bc4 = (tid & 15) * 4;
    const float* bP0 = Be + (size_t)(2 * bk2) * HDIM + n0 + bc4;
    const float* bP1 = bP0 + HDIM;

    int w = tid >> 5, lane = tid & 31;
    int g = lane >> 2, t = lane & 3;
    int wm = (w & 1) * 64, wn = (w >> 1) * 64;

    float ac[4][8][4];
    #pragma unroll
    for (int i = 0; i < 4; i++)
        #pragma unroll
        for (int j = 0; j < 8; j++)
            #pragma unroll
            for (int q = 0; q < 4; q++) ac[i][j][q] = 0.f;

    uint4 pa[2];
    float4 pb0[4], pb1[4];
    #pragma unroll
    for (int i = 0; i < 2; i++) pa[i] = *(const uint4*)(aP + 8 * i);
    #pragma unroll
    for (int i = 0; i < 4; i++) {
        pb0[i] = *(const float4*)(bP0 + 64 * i);
        pb1[i] = *(const float4*)(bP1 + 64 * i);
    }

    const int NK = K / 32;
    for (int it = 0; it < NK; ++it) {
        {
            *(uint4*)&As[arow * SAW + kw]     = pa[0];
            *(uint4*)&As[arow * SAW + kw + 4] = pa[1];
            #pragma unroll
            for (int i = 0; i < 4; i++) {
                uint4 bb;
                bb.x = h2(pb0[i].x, pb1[i].x); bb.y = h2(pb0[i].y, pb1[i].y);
                bb.z = h2(pb0[i].z, pb1[i].z); bb.w = h2(pb0[i].w, pb1[i].w);
                *(uint4*)&Bs[bk2 * SBD + bc4 + 64 * i] = bb;
            }
        }
        __syncthreads();

        if (it + 1 < NK) {
            const __half* aN = aP + (it + 1) * 32;
            const float* bN0 = bP0 + (size_t)(it + 1) * 32 * HDIM;
            const float* bN1 = bN0 + HDIM;
            #pragma unroll
            for (int i = 0; i < 2; i++) pa[i] = *(const uint4*)(aN + 8 * i);
            #pragma unroll
            for (int i = 0; i < 4; i++) {
                pb0[i] = *(const float4*)(bN0 + 64 * i);
                pb1[i] = *(const float4*)(bN1 + 64 * i);
            }
        }

        #pragma unroll
        for (int ks = 0; ks < 2; ++ks) {
            int k0 = ks * 8;
            u32 af[4][4];
            #pragma unroll
            for (int mt = 0; mt < 4; ++mt) {
                int r = wm + mt * 16 + g;
                af[mt][0] = As[r * SAW + k0 + t];
                af[mt][1] = As[(r + 8) * SAW + k0 + t];
                af[mt][2] = As[r * SAW + k0 + t + 4];
                af[mt][3] = As[(r + 8) * SAW + k0 + t + 4];
            }
            #pragma unroll
            for (int nt = 0; nt < 8; ++nt) {
                int n = wn + nt * 8 + g;
                u32 bf2[2] = { Bs[(k0 + t) * SBD + n], Bs[(k0 + t + 4) * SBD + n] };
                #pragma unroll
                for (int mt = 0; mt < 4; ++mt)
                    mma16(ac[mt][nt], af[mt], bf2);
            }
        }
        __syncthreads();
    }

    #pragma unroll
    for (int mt = 0; mt < 4; ++mt) {
        int l0 = wm + mt * 16 + g;
        int s0 = m0 + l0, s1 = s0 + 8;
        bool v0 = s0 < cn, v1 = s1 < cn;
        float* o0 = OUT + (size_t)tokSm[l0] * HDIM + n0 + wn;
        float* o1 = OUT + (size_t)tokSm[l0 + 8] * HDIM + n0 + wn;
        #pragma unroll
        for (int nt = 0; nt < 8; ++nt) {
            int c = nt * 8 + 2 * t;
            if (v0) { atomicAdd(o0 + c, ac[mt][nt][0]); atomicAdd(o0 + c + 1, ac[mt][nt][1]); }
            if (v1) { atomicAdd(o1 + c, ac[mt][nt][2]); atomicAdd(o1 + c + 1, ac[mt][nt][3]); }
        }
    }
}

// ---------------- launch ----------------
extern "C" void kernel_launch(void* const* d_in, const int* in_sizes, int n_in,
                              void* d_out, int out_size)
{
    const float* x    = (const float*)d_in[0];
    const float* gw   = (const float*)d_in[1];
    const float* bias = (const float*)d_in[2];
    const float* wgu  = (const float*)d_in[3];
    const float* wdn  = (const float*)d_in[4];
    const float* sgu  = (const float*)d_in[5];
    const float* sdn  = (const float*)d_in[6];
    float* out = (float*)d_out;

    void *p_cnt, *p_tok, *p_tw, *p_t4, *p_w4, *p_act, *p_acts;
    cudaGetSymbolAddress(&p_cnt,  g_cnt);
    cudaGetSymbolAddress(&p_tok,  g_tok);
    cudaGetSymbolAddress(&p_tw,   g_tw);
    cudaGetSymbolAddress(&p_t4,   g_tid4);
    cudaGetSymbolAddress(&p_w4,   g_twk4);
    cudaGetSymbolAddress(&p_act,  g_act);
    cudaGetSymbolAddress(&p_acts, g_acts);

    // 0) zero-init out (both down parts accumulate atomically)
    zero_out<<<(T_TOK * HDIM / 4 + 255) / 256, 256>>>((float4*)out, T_TOK * HDIM / 4);

    // 1) router + deterministic dispatch lists (exact fp32)
    router_kernel<<<T_TOK, 128>>>(x, gw, bias, (int*)p_t4, (float*)p_w4);
    build_lists<<<1, 16>>>((const int*)p_t4, (const float*)p_w4,
                           (int*)p_cnt, (int*)p_tok, (float*)p_tw);

    // 2) combined gate_up + silu (routed z<16, shared z=16)
    gu_comb<<<dim3(SI / 128, T_TOK / 128, NEXP + 1), 256>>>(
        x, wgu, sgu, (__half*)p_act, (__half*)p_acts,
        (const int*)p_tok, (const float*)p_tw, (const int*)p_cnt);

    // 3) combined down-proj (routed z<16, shared z=16), atomic accumulate
    down_comb<<<dim3(HDIM / 256, T_TOK / 128, NEXP + 1), 256>>>(
        (const __half*)p_act, (const __half*)p_acts, wdn, sdn, out,
        (const int*)p_tok, (const int*)p_cnt);
}

// round 16
// speedup vs baseline: 1.1714x; 1.0460x over previous
#include <cuda_runtime.h>
#include <cuda_fp16.h>
#include <cstdint>

#define T_TOK 1024
#define HDIM  2048
#define NEXP  16
#define IDIM  1408
#define SI    2816
#define TOPK  4
#define KD    1408   // down-proj K per CTA (routed full K; shared half K)

typedef unsigned long long ull;
typedef unsigned int u32;

// ---------------- scratch (device globals; no allocation allowed) ----------------
__device__ int    g_cnt[NEXP];
__device__ int    g_tok[NEXP * T_TOK];
__device__ float  g_tw [NEXP * T_TOK];
__device__ int    g_tid4[T_TOK * TOPK];
__device__ float  g_twk4[T_TOK * TOPK];
__device__ __half g_act [(size_t)NEXP * T_TOK * IDIM];  // routed activations (fp16)
__device__ __half g_acts[(size_t)T_TOK * SI];           // shared activations (fp16)

// ---------------- helpers ----------------
__device__ __forceinline__ u32 h2(float lo, float hi) {
    __half2 h = __floats2half2_rn(lo, hi);
    return *reinterpret_cast<u32*>(&h);
}
// fp16 MMA m16n8k16, fp32 accumulate
__device__ __forceinline__ void mma16(float* d, const u32* a, const u32* b) {
    asm volatile(
        "mma.sync.aligned.m16n8k16.row.col.f32.f16.f16.f32 "
        "{%0,%1,%2,%3}, {%4,%5,%6,%7}, {%8,%9}, {%0,%1,%2,%3};"
        : "+f"(d[0]), "+f"(d[1]), "+f"(d[2]), "+f"(d[3])
        : "r"(a[0]), "r"(a[1]), "r"(a[2]), "r"(a[3]), "r"(b[0]), "r"(b[1]));
}
__device__ __forceinline__ float silu_f(float g) { return g / (1.f + expf(-g)); }

// ---------------- zero-init of out ----------------
__global__ void zero_out(float4* __restrict__ p, int n)
{
    int i = blockIdx.x * blockDim.x + threadIdx.x;
    if (i < n) p[i] = make_float4(0.f, 0.f, 0.f, 0.f);
}

// ---------------- router (exact fp32) ----------------
__global__ void router_kernel(const float* __restrict__ x,
                              const float* __restrict__ gw,
                              const float* __restrict__ bias,
                              int* __restrict__ tid4, float* __restrict__ twk4)
{
    int t = blockIdx.x;
    int tid = threadIdx.x;            // 128 threads: 16 experts x 8 lanes
    int e = tid >> 3, r = tid & 7;
    const float4* x4 = reinterpret_cast<const float4*>(x + (size_t)t * HDIM);
    const float4* w4 = reinterpret_cast<const float4*>(gw + (size_t)e * HDIM);
    float s = 0.f;
    #pragma unroll 4
    for (int j = r; j < HDIM / 4; j += 8) {
        float4 a = x4[j], b = w4[j];
        s += a.x * b.x + a.y * b.y + a.z * b.z + a.w * b.w;
    }
    #pragma unroll
    for (int o = 4; o > 0; o >>= 1) s += __shfl_down_sync(0xffffffffu, s, o, 8);
    __shared__ float logit[NEXP];
    if (r == 0) logit[e] = s;
    __syncthreads();
    if (tid == 0) {
        float sc[NEXP], sb[NEXP];
        #pragma unroll
        for (int i = 0; i < NEXP; i++) {
            sc[i] = 1.f / (1.f + expf(-logit[i]));
            sb[i] = sc[i] + bias[i];
        }
        float gsc[4];
        #pragma unroll
        for (int g = 0; g < 4; g++) {
            const float* p = sb + g * 4;
            float m1 = p[0]; int i1 = 0;
            for (int i = 1; i < 4; i++) if (p[i] > m1) { m1 = p[i]; i1 = i; }
            float m2 = -1e30f;
            for (int i = 0; i < 4; i++) if (i != i1 && p[i] > m2) m2 = p[i];
            gsc[g] = m1 + m2;
        }
        int g1 = 0; for (int g = 1; g < 4; g++) if (gsc[g] > gsc[g1]) g1 = g;
        int g2 = (g1 == 0) ? 1 : 0;
        for (int g = 0; g < 4; g++) if (g != g1 && gsc[g] > gsc[g2]) g2 = g;
        bool allow[NEXP];
        for (int i = 0; i < NEXP; i++) { int g = i >> 2; allow[i] = (g == g1 || g == g2); }
        int ids[TOPK]; float wsum = 0.f;
        for (int k = 0; k < TOPK; k++) {
            int best = 0; float bv = -1e30f;
            for (int i = 0; i < NEXP; i++)
                if (allow[i] && sb[i] > bv) { bv = sb[i]; best = i; }
            allow[best] = false;
            ids[k] = best;
            wsum += sc[best];
        }
        for (int k = 0; k < TOPK; k++) {
            tid4[t * TOPK + k] = ids[k];
            twk4[t * TOPK + k] = sc[ids[k]] / wsum;
        }
    }
}

// ---------------- deterministic per-expert token lists ----------------
__global__ void build_lists(const int* __restrict__ tid4, const float* __restrict__ twk4,
                            int* __restrict__ cnt, int* __restrict__ tok, float* __restrict__ tw)
{
    int e = threadIdx.x;
    if (e >= NEXP) return;
    int c = 0;
    for (int t = 0; t < T_TOK; t++) {
        int4  id = reinterpret_cast<const int4*>(tid4)[t];
        float4 w = reinterpret_cast<const float4*>(twk4)[t];
        if (id.x == e) { tok[e * T_TOK + c] = t; tw[e * T_TOK + c] = w.x * 2.5f; c++; }
        if (id.y == e) { tok[e * T_TOK + c] = t; tw[e * T_TOK + c] = w.y * 2.5f; c++; }
        if (id.z == e) { tok[e * T_TOK + c] = t; tw[e * T_TOK + c] = w.z * 2.5f; c++; }
        if (id.w == e) { tok[e * T_TOK + c] = t; tw[e * T_TOK + c] = w.w * 2.5f; c++; }
    }
    cnt[e] = c;
}

// =====================================================================
// COMBINED gate_up GEMM (routed z<16 + shared z==16 in one launch).
// fp16 mma.sync m16n8k16; CTA tile 128m x (128g+128u); 8 warps = 2m x 4n;
// warp tile 64m x (32g + 32u). act = silu(g)*u*w (fp16 out).
// =====================================================================
#define SAW 20
#define SBW 136
__global__ void __launch_bounds__(256)
gu_comb(const float* __restrict__ X,
        const float* __restrict__ Wr, const float* __restrict__ Ws,
        __half* __restrict__ ACTr, __half* __restrict__ ACTs,
        const int* __restrict__ tok, const float* __restrict__ tw,
        const int* __restrict__ cnt)
{
    __shared__ u32 As[128 * SAW];
    __shared__ u32 Bg[16 * SBW];
    __shared__ u32 Bu[16 * SBW];
    __shared__ int   tokSm[128];
    __shared__ float twSm[128];

    int z = blockIdx.z;
    bool routed = (z < NEXP);
    if (routed && blockIdx.x >= IDIM / 128) return;
    int Iw = routed ? IDIM : SI;
    int e  = routed ? z : 0;
    int cn = routed ? cnt[e] : T_TOK;
    int m0 = blockIdx.y * 128;
    if (m0 >= cn) return;
    int n0 = blockIdx.x * 128;
    const int K = HDIM;
    int ldW = 2 * Iw;
    const float* We = routed ? (Wr + (size_t)e * K * ldW) : Ws;
    __half* actE = routed ? (ACTr + (size_t)e * T_TOK * IDIM) : ACTs;
    const int*   tokE = routed ? (tok + e * T_TOK) : nullptr;
    const float* twE  = routed ? (tw  + e * T_TOK) : nullptr;

    int tid = threadIdx.x;
    if (tid < 128) {
        int s = m0 + tid; int a; float wv;
        if (routed) {
            if (s < cn) { a = tokE[s]; wv = twE[s]; } else { a = 0; wv = 0.f; }
        } else { a = s; wv = 1.f; }
        tokSm[tid] = a; twSm[tid] = wv;
    }
    __syncthreads();

    // staging mapping
    int arow = tid >> 1, kw = (tid & 1) * 8;
    const float* aP = X + (size_t)tokSm[arow] * K + kw * 2;
    int bk2 = tid >> 4, bn = (tid & 15) * 4;
    const float* gP0 = We + (size_t)(2 * bk2) * ldW + n0 + bn;
    const float* gP1 = gP0 + ldW;
    const float* uP0 = gP0 + Iw;
    const float* uP1 = gP1 + Iw;

    // warp mapping: 2m x 4n
    int w = tid >> 5, lane = tid & 31;
    int g = lane >> 2, t = lane & 3;
    int wm = (w & 1) * 64, wn = (w >> 1) * 32;

    float ag[4][4][4], au[4][4][4];
    #pragma unroll
    for (int i = 0; i < 4; i++)
        #pragma unroll
        for (int j = 0; j < 4; j++)
            #pragma unroll
            for (int q = 0; q < 4; q++) { ag[i][j][q] = 0.f; au[i][j][q] = 0.f; }

    float4 pa[4];
    float4 pg0[2], pg1[2], pu0[2], pu1[2];
    #pragma unroll
    for (int i = 0; i < 4; i++) pa[i] = *(const float4*)(aP + 4 * i);
    #pragma unroll
    for (int i = 0; i < 2; i++) {
        pg0[i] = *(const float4*)(gP0 + 64 * i);
        pg1[i] = *(const float4*)(gP1 + 64 * i);
        pu0[i] = *(const float4*)(uP0 + 64 * i);
        pu1[i] = *(const float4*)(uP1 + 64 * i);
    }

    const int NK = K / 32;
    for (int it = 0; it < NK; ++it) {
        {
            uint4 w0, w1;
            w0.x = h2(pa[0].x, pa[0].y); w0.y = h2(pa[0].z, pa[0].w);
            w0.z = h2(pa[1].x, pa[1].y); w0.w = h2(pa[1].z, pa[1].w);
            w1.x = h2(pa[2].x, pa[2].y); w1.y = h2(pa[2].z, pa[2].w);
            w1.z = h2(pa[3].x, pa[3].y); w1.w = h2(pa[3].z, pa[3].w);
            *(uint4*)&As[arow * SAW + kw]     = w0;
            *(uint4*)&As[arow * SAW + kw + 4] = w1;
            #pragma unroll
            for (int i = 0; i < 2; i++) {
                uint4 bg, bu;
                bg.x = h2(pg0[i].x, pg1[i].x); bg.y = h2(pg0[i].y, pg1[i].y);
                bg.z = h2(pg0[i].z, pg1[i].z); bg.w = h2(pg0[i].w, pg1[i].w);
                bu.x = h2(pu0[i].x, pu1[i].x); bu.y = h2(pu0[i].y, pu1[i].y);
                bu.z = h2(pu0[i].z, pu1[i].z); bu.w = h2(pu0[i].w, pu1[i].w);
                *(uint4*)&Bg[bk2 * SBW + bn + 64 * i] = bg;
                *(uint4*)&Bu[bk2 * SBW + bn + 64 * i] = bu;
            }
        }
        __syncthreads();

        if (it + 1 < NK) {
            const float* aN  = aP + (it + 1) * 32;
            const float* gN0 = gP0 + (size_t)(it + 1) * 32 * ldW;
            const float* gN1 = gN0 + ldW;
            const float* uN0 = gN0 + Iw;
            const float* uN1 = gN1 + Iw;
            #pragma unroll
            for (int i = 0; i < 4; i++) pa[i] = *(const float4*)(aN + 4 * i);
            #pragma unroll
            for (int i = 0; i < 2; i++) {
                pg0[i] = *(const float4*)(gN0 + 64 * i);
                pg1[i] = *(const float4*)(gN1 + 64 * i);
                pu0[i] = *(const float4*)(uN0 + 64 * i);
                pu1[i] = *(const float4*)(uN1 + 64 * i);
            }
        }

        #pragma unroll
        for (int ks = 0; ks < 2; ++ks) {
            int k0 = ks * 8;
            u32 af[4][4];
            #pragma unroll
            for (int mt = 0; mt < 4; ++mt) {
                int r = wm + mt * 16 + g;
                af[mt][0] = As[r * SAW + k0 + t];
                af[mt][1] = As[(r + 8) * SAW + k0 + t];
                af[mt][2] = As[r * SAW + k0 + t + 4];
                af[mt][3] = As[(r + 8) * SAW + k0 + t + 4];
            }
            #pragma unroll
            for (int nt = 0; nt < 4; ++nt) {
                int n = wn + nt * 8 + g;
                u32 bg2[2] = { Bg[(k0 + t) * SBW + n], Bg[(k0 + t + 4) * SBW + n] };
                u32 bu2[2] = { Bu[(k0 + t) * SBW + n], Bu[(k0 + t + 4) * SBW + n] };
                #pragma unroll
                for (int mt = 0; mt < 4; ++mt) {
                    mma16(ag[mt][nt], af[mt], bg2);
                    mma16(au[mt][nt], af[mt], bu2);
                }
            }
        }
        __syncthreads();
    }

    // epilogue: silu(g)*u*w -> act (fp16)
    #pragma unroll
    for (int mt = 0; mt < 4; ++mt) {
        int l0 = wm + mt * 16 + g;
        int s0 = m0 + l0, s1 = s0 + 8;
        bool v0 = s0 < cn, v1 = s1 < cn;
        float w0 = twSm[l0], w1 = twSm[l0 + 8];
        __half* o0 = actE + (size_t)s0 * Iw + n0 + wn;
        __half* o1 = actE + (size_t)s1 * Iw + n0 + wn;
        #pragma unroll
        for (int nt = 0; nt < 4; ++nt) {
            int c = nt * 8 + 2 * t;
            if (v0) {
                *(u32*)(o0 + c) = h2(silu_f(ag[mt][nt][0]) * au[mt][nt][0] * w0,
                                     silu_f(ag[mt][nt][1]) * au[mt][nt][1] * w0);
            }
            if (v1) {
                *(u32*)(o1 + c) = h2(silu_f(ag[mt][nt][2]) * au[mt][nt][2] * w1,
                                     silu_f(ag[mt][nt][3]) * au[mt][nt][3] * w1);
            }
        }
    }
}

// =====================================================================
// COMBINED down-proj GEMM, EQUALIZED CTA DURATIONS (all K=1408 per CTA):
//   z==0,1 : shared down, K-half z (koff = z*1408), dispatched FIRST
//   z>=2   : routed expert e=z-2, full K=1408
// CTA tile 128m x 256n; 8 warps = 2m x 4n; warp tile 64m x 64n.
// All outputs atomicAdd into zero-initialized out.
// =====================================================================
#define SBD 264
__global__ void __launch_bounds__(256)
down_comb(const __half* __restrict__ Ar, const __half* __restrict__ Ash,
          const float* __restrict__ Wr, const float* __restrict__ Ws,
          float* __restrict__ OUT,
          const int* __restrict__ tok, const int* __restrict__ cnt)
{
    __shared__ u32 As[128 * SAW];
    __shared__ u32 Bs[16 * SBD];
    __shared__ int tokSm[128];

    int z = blockIdx.z;
    bool routed = (z >= 2);
    int e  = z - 2;
    int cn = routed ? cnt[e] : T_TOK;
    int m0 = blockIdx.y * 128;
    if (m0 >= cn) return;
    int n0 = blockIdx.x * 256;
    int lda  = routed ? IDIM : SI;          // A row stride (halves)
    int koff = routed ? 0 : z * KD;         // K offset for shared halves
    const __half* Ae = routed ? (Ar + (size_t)e * T_TOK * IDIM) : Ash;
    const float*  Be = routed ? (Wr + (size_t)e * (size_t)IDIM * HDIM)
                              : (Ws + (size_t)koff * HDIM);

    int tid = threadIdx.x;
    if (tid < 128) {
        int s = m0 + tid;
        tokSm[tid] = routed ? ((s < cn) ? tok[e * T_TOK + s] : 0) : s;
    }
    __syncthreads();

    int arow = tid >> 1, kw = (tid & 1) * 8;
    const __half* aP = Ae + (size_t)(m0 + arow) * lda + koff + kw * 2;
    int bk2 = tid >> 4, bc4 = (tid & 15) * 4;
    const float* bP0 = Be + (size_t)(2 * bk2) * HDIM + n0 + bc4;
    const float* bP1 = bP0 + HDIM;

    int w = tid >> 5, lane = tid & 31;
    int g = lane >> 2, t = lane & 3;
    int wm = (w & 1) * 64, wn = (w >> 1) * 64;

    float ac[4][8][4];
    #pragma unroll
    for (int i = 0; i < 4; i++)
        #pragma unroll
        for (int j = 0; j < 8; j++)
            #pragma unroll
            for (int q = 0; q < 4; q++) ac[i][j][q] = 0.f;

    uint4 pa[2];
    float4 pb0[4], pb1[4];
    #pragma unroll
    for (int i = 0; i < 2; i++) pa[i] = *(const uint4*)(aP + 8 * i);
    #pragma unroll
    for (int i = 0; i < 4; i++) {
        pb0[i] = *(const float4*)(bP0 + 64 * i);
        pb1[i] = *(const float4*)(bP1 + 64 * i);
    }

    const int NK = KD / 32;   // 44 for every CTA
    for (int it = 0; it < NK; ++it) {
        {
            *(uint4*)&As[arow * SAW + kw]     = pa[0];
            *(uint4*)&As[arow * SAW + kw + 4] = pa[1];
            #pragma unroll
            for (int i = 0; i < 4; i++) {
                uint4 bb;
                bb.x = h2(pb0[i].x, pb1[i].x); bb.y = h2(pb0[i].y, pb1[i].y);
                bb.z = h2(pb0[i].z, pb1[i].z); bb.w = h2(pb0[i].w, pb1[i].w);
                *(uint4*)&Bs[bk2 * SBD + bc4 + 64 * i] = bb;
            }
        }
        __syncthreads();

        if (it + 1 < NK) {
            const __half* aN = aP + (it + 1) * 32;
            const float* bN0 = bP0 + (size_t)(it + 1) * 32 * HDIM;
            const float* bN1 = bN0 + HDIM;
            #pragma unroll
            for (int i = 0; i < 2; i++) pa[i] = *(const uint4*)(aN + 8 * i);
            #pragma unroll
            for (int i = 0; i < 4; i++) {
                pb0[i] = *(const float4*)(bN0 + 64 * i);
                pb1[i] = *(const float4*)(bN1 + 64 * i);
            }
        }

        #pragma unroll
        for (int ks = 0; ks < 2; ++ks) {
            int k0 = ks * 8;
            u32 af[4][4];
            #pragma unroll
            for (int mt = 0; mt < 4; ++mt) {
                int r = wm + mt * 16 + g;
                af[mt][0] = As[r * SAW + k0 + t];
                af[mt][1] = As[(r + 8) * SAW + k0 + t];
                af[mt][2] = As[r * SAW + k0 + t + 4];
                af[mt][3] = As[(r + 8) * SAW + k0 + t + 4];
            }
            #pragma unroll
            for (int nt = 0; nt < 8; ++nt) {
                int n = wn + nt * 8 + g;
                u32 bf2[2] = { Bs[(k0 + t) * SBD + n], Bs[(k0 + t + 4) * SBD + n] };
                #pragma unroll
                for (int mt = 0; mt < 4; ++mt)
                    mma16(ac[mt][nt], af[mt], bf2);
            }
        }
        __syncthreads();
    }

    #pragma unroll
    for (int mt = 0; mt < 4; ++mt) {
        int l0 = wm + mt * 16 + g;
        int s0 = m0 + l0, s1 = s0 + 8;
        bool v0 = s0 < cn, v1 = s1 < cn;
        float* o0 = OUT + (size_t)tokSm[l0] * HDIM + n0 + wn;
        float* o1 = OUT + (size_t)tokSm[l0 + 8] * HDIM + n0 + wn;
        #pragma unroll
        for (int nt = 0; nt < 8; ++nt) {
            int c = nt * 8 + 2 * t;
            if (v0) { atomicAdd(o0 + c, ac[mt][nt][0]); atomicAdd(o0 + c + 1, ac[mt][nt][1]); }
            if (v1) { atomicAdd(o1 + c, ac[mt][nt][2]); atomicAdd(o1 + c + 1, ac[mt][nt][3]); }
        }
    }
}

// ---------------- launch ----------------
extern "C" void kernel_launch(void* const* d_in, const int* in_sizes, int n_in,
                              void* d_out, int out_size)
{
    const float* x    = (const float*)d_in[0];
    const float* gw   = (const float*)d_in[1];
    const float* bias = (const float*)d_in[2];
    const float* wgu  = (const float*)d_in[3];
    const float* wdn  = (const float*)d_in[4];
    const float* sgu  = (const float*)d_in[5];
    const float* sdn  = (const float*)d_in[6];
    float* out = (float*)d_out;

    void *p_cnt, *p_tok, *p_tw, *p_t4, *p_w4, *p_act, *p_acts;
    cudaGetSymbolAddress(&p_cnt,  g_cnt);
    cudaGetSymbolAddress(&p_tok,  g_tok);
    cudaGetSymbolAddress(&p_tw,   g_tw);
    cudaGetSymbolAddress(&p_t4,   g_tid4);
    cudaGetSymbolAddress(&p_w4,   g_twk4);
    cudaGetSymbolAddress(&p_act,  g_act);
    cudaGetSymbolAddress(&p_acts, g_acts);

    // 0) zero-init out (all down parts accumulate atomically)
    zero_out<<<(T_TOK * HDIM / 4 + 255) / 256, 256>>>((float4*)out, T_TOK * HDIM / 4);

    // 1) router + deterministic dispatch lists (exact fp32)
    router_kernel<<<T_TOK, 128>>>(x, gw, bias, (int*)p_t4, (float*)p_w4);
    build_lists<<<1, 16>>>((const int*)p_t4, (const float*)p_w4,
                           (int*)p_cnt, (int*)p_tok, (float*)p_tw);

    // 2) combined gate_up + silu (routed z<16, shared z=16)
    gu_comb<<<dim3(SI / 128, T_TOK / 128, NEXP + 1), 256>>>(
        x, wgu, sgu, (__half*)p_act, (__half*)p_acts,
        (const int*)p_tok, (const float*)p_tw, (const int*)p_cnt);

    // 3) combined down-proj, equal-duration CTAs:
    //    z=0,1 shared K-halves (first), z=2..17 routed experts
    down_comb<<<dim3(HDIM / 256, T_TOK / 128, NEXP + 2), 256>>>(
        (const __half*)p_act, (const __half*)p_acts, wdn, sdn, out,
        (const int*)p_tok, (const int*)p_cnt);
}